// round 1
// baseline (speedup 1.0000x reference)
#include <cuda_runtime.h>
#include <math.h>
#include <stdint.h>

#define NB 32
#define NG 16
#define NA 8400
#define NCLS 80
#define CAND 10

// ---------------- scratch (device globals; no allocation allowed) ----------
__device__ float         g_cost[(size_t)NB * NG * NA];   // unmasked cost
__device__ float         g_iou [(size_t)NB * NG * NA];   // raw pairwise iou
__device__ float         g_pbox[(size_t)NB * NA * 4];
__device__ float         g_conf[(size_t)NB * NA];
__device__ unsigned char g_union[(size_t)NB * NA];
__device__ int           g_best[(size_t)NB * NA];        // argmin_g masked cost
__device__ int           g_cnt [(size_t)NB * NA];
__device__ int           g_gsum[(size_t)NB * NA];
__device__ int           g_sel [NB * NG * CAND];
__device__ int           g_dynk[NB * NG];
__device__ double        g_acc[4];   // loss_box, loss_conf, loss_cls, n_fg

static __device__ __forceinline__ unsigned long long umin64(unsigned long long a,
                                                            unsigned long long b) {
    return a < b ? a : b;
}

static __device__ __forceinline__ void level_of(int a, int b,
                                                const float* p8, const float* p16, const float* p32,
                                                const float** P, int* HW, int* loc, float* s, int* w) {
    if (a < 6400)      { *P = p8  + (size_t)b * 85 * 6400; *HW = 6400; *loc = a;        *s = 8.f;  *w = 80; }
    else if (a < 8000) { *P = p16 + (size_t)b * 85 * 1600; *HW = 1600; *loc = a - 6400; *s = 16.f; *w = 40; }
    else               { *P = p32 + (size_t)b * 85 * 400;  *HW = 400;  *loc = a - 8000; *s = 32.f; *w = 20; }
}

// ---------------- kernel A: decode + cost/iou matrices ---------------------
__global__ void kA(const float* __restrict__ p8, const float* __restrict__ p16,
                   const float* __restrict__ p32, const float* __restrict__ gtb,
                   const int* __restrict__ gtc) {
    int b   = blockIdx.y;
    int tid = threadIdx.x;
    int a   = blockIdx.x * blockDim.x + tid;

    __shared__ float sB[NG * 4];
    __shared__ int   sC[NG];
    if (tid < NG * 4) sB[tid] = gtb[b * NG * 4 + tid];
    if (tid < NG)     sC[tid] = gtc[b * NG + tid];
    __syncthreads();
    if (a >= NA) return;

    const float* P; int HW, loc, w; float s;
    level_of(a, b, p8, p16, p32, &P, &HW, &loc, &s, &w);
    P += loc;
    int ix = loc % w, iy = loc / w;

    float px = P[0], py = P[HW], pw = P[2 * HW], ph = P[3 * HW], cf = P[4 * HW];
    float bx = (px + (float)ix) * s;
    float by = (py + (float)iy) * s;
    float bw = expf(pw) * s;   // decode uses exp; keep precise (feeds IoU -> dyn_k and loss)
    float bh = expf(ph) * s;
    float xc = ((float)ix + 0.5f) * s;
    float yc = ((float)iy + 0.5f) * s;

    float sc = 1.f / (1.f + __expf(-cf));   // selection-only from here on: fast intrinsics OK

    float suml1 = 0.f;
    #pragma unroll 4
    for (int c = 0; c < NCLS; c++) {
        float x  = P[(5 + c) * HW];
        float sg = 1.f / (1.f + __expf(-x));
        float p  = sqrtf(sg * sc);
        float l1 = fmaxf(__logf(fmaxf(1.f - p, 1e-12f)), -100.f);
        suml1 += l1;
    }

    float areab = bw * bh;
    float bhw = bw * 0.5f, bhh = bh * 0.5f;
    float r = 2.5f * s;
    bool  uni = false;
    float bestc = 3.402823466e38f;
    int   bestg = 0;
    size_t base = ((size_t)b * NG) * NA + a;

    for (int g = 0; g < NG; g++) {
        float cx = sB[g * 4 + 0], cy = sB[g * 4 + 1];
        float gw = sB[g * 4 + 2], gh = sB[g * 4 + 3];
        int   c  = sC[g];
        float x  = P[(5 + c) * HW];
        float sg = 1.f / (1.f + __expf(-x));
        float p  = sqrtf(sg * sc);
        float lp = fmaxf(__logf(fmaxf(p, 1e-12f)), -100.f);
        float l1 = fmaxf(__logf(fmaxf(1.f - p, 1e-12f)), -100.f);
        float cls_cost = -(lp - l1 + suml1);

        float gminx = cx - gw * 0.5f, gmaxx = cx + gw * 0.5f;
        float gminy = cy - gh * 0.5f, gmaxy = cy + gh * 0.5f;
        float tlx = fmaxf(gminx, bx - bhw), tly = fmaxf(gminy, by - bhh);
        float brx = fminf(gmaxx, bx + bhw), bry = fminf(gmaxy, by + bhh);
        float iw = fmaxf(brx - tlx, 0.f), ih = fmaxf(bry - tly, 0.f);
        float inter = iw * ih;
        float iou = inter / (gw * gh + areab - inter + 1e-16f);

        bool inb = (xc - gminx > 0.f) && (gmaxx - xc > 0.f) &&
                   (yc - gminy > 0.f) && (gmaxy - yc > 0.f);
        bool inm = (xc - (cx - r) > 0.f) && ((cx + r) - xc > 0.f) &&
                   (yc - (cy - r) > 0.f) && ((cy + r) - yc > 0.f);

        float cost = cls_cost + 3.f * (-__logf(iou + 1e-8f)) +
                     ((inb && inm) ? 0.f : 100000.f);
        uni = uni || inb || inm;
        if (cost < bestc) { bestc = cost; bestg = g; }   // strict < == argmin first-index

        g_cost[base + (size_t)g * NA] = cost;
        g_iou [base + (size_t)g * NA] = iou;
    }

    int idx = b * NA + a;
    g_union[idx] = uni ? 1 : 0;
    g_best[idx]  = uni ? bestg : 0;   // masked-argmin == 0 when all rows are 1e15
    g_conf[idx]  = cf;
    g_pbox[idx * 4 + 0] = bx; g_pbox[idx * 4 + 1] = by;
    g_pbox[idx * 4 + 2] = bw; g_pbox[idx * 4 + 3] = bh;
}

// ---------------- kernel B: per-(b,g) top-k (cost asc / iou desc) ----------
__global__ void kB() {
    const int T = 256;
    int bg  = blockIdx.x;          // b*16 + g
    int b   = bg >> 4;
    int tid = threadIdx.x;
    size_t cbase = (size_t)bg * NA;
    size_t ubase = (size_t)b * NA;

    unsigned long long keys[CAND], ikeys[CAND];
    #pragma unroll
    for (int k = 0; k < CAND; k++) { keys[k] = ~0ull; ikeys[k] = ~0ull; }

    for (int a = tid; a < NA; a += T) {
        bool u = g_union[ubase + a] != 0;
        // --- cost key: ordered-float-bits<<32 | idx  => (cost asc, idx asc) ---
        float cost = u ? g_cost[cbase + a] : 1e15f;
        unsigned cb = __float_as_uint(cost);
        cb = (cb & 0x80000000u) ? ~cb : (cb | 0x80000000u);
        unsigned long long key = (((unsigned long long)cb) << 32) | (unsigned)a;
        #pragma unroll
        for (int k = 0; k < CAND; k++)
            if (key < keys[k]) { unsigned long long t = keys[k]; keys[k] = key; key = t; }
        // --- iou key (values >= 0): descending via ~ascending ---
        float im = u ? g_iou[cbase + a] : 0.f;
        unsigned ib = ~(__float_as_uint(im) | 0x80000000u);
        unsigned long long ikey = (((unsigned long long)ib) << 32) | (unsigned)a;
        #pragma unroll
        for (int k = 0; k < CAND; k++)
            if (ikey < ikeys[k]) { unsigned long long t = ikeys[k]; ikeys[k] = ikey; ikey = t; }
    }

    __shared__ unsigned long long sk[T * CAND];
    __shared__ unsigned long long red[T];

    // ---- extract 10 smallest cost keys ----
    #pragma unroll
    for (int k = 0; k < CAND; k++) sk[tid * CAND + k] = keys[k];
    __syncthreads();
    for (int k = 0; k < CAND; k++) {
        unsigned long long m = ~0ull;
        for (int j = tid; j < T * CAND; j += T) m = umin64(m, sk[j]);
        red[tid] = m; __syncthreads();
        for (int off = T / 2; off > 0; off >>= 1) {
            if (tid < off) red[tid] = umin64(red[tid], red[tid + off]);
            __syncthreads();
        }
        unsigned long long best = red[0];
        if (tid == 0) g_sel[bg * CAND + k] = (int)(best & 0xffffffffu);
        for (int j = tid; j < T * CAND; j += T) if (sk[j] == best) sk[j] = ~0ull;
        __syncthreads();
    }

    // ---- extract 10 largest masked ious, sum -> dyn_k ----
    #pragma unroll
    for (int k = 0; k < CAND; k++) sk[tid * CAND + k] = ikeys[k];
    __syncthreads();
    float sum = 0.f;
    for (int k = 0; k < CAND; k++) {
        unsigned long long m = ~0ull;
        for (int j = tid; j < T * CAND; j += T) m = umin64(m, sk[j]);
        red[tid] = m; __syncthreads();
        for (int off = T / 2; off > 0; off >>= 1) {
            if (tid < off) red[tid] = umin64(red[tid], red[tid + off]);
            __syncthreads();
        }
        unsigned long long best = red[0];
        unsigned key32 = (unsigned)(best >> 32);
        sum += __uint_as_float((~key32) & 0x7fffffffu);
        for (int j = tid; j < T * CAND; j += T) if (sk[j] == best) sk[j] = ~0ull;
        __syncthreads();
    }
    if (tid == 0) {
        int dk = (int)sum;           // trunc toward zero, matches astype(int32)
        g_dynk[bg] = dk < 1 ? 1 : dk;
    }
}

// ---------------- init scratch ----------------------------------------------
__global__ void kInit() {
    int i = blockIdx.x * blockDim.x + threadIdx.x;
    if (i < NB * NA) { g_cnt[i] = 0; g_gsum[i] = 0; }
    if (i < 4) g_acc[i] = 0.0;
}

// ---------------- scatter selections ----------------------------------------
__global__ void kScatter() {
    int e = blockIdx.x * blockDim.x + threadIdx.x;
    if (e >= NB * NG * CAND) return;
    int k  = e % CAND;
    int bg = e / CAND;
    if (k < g_dynk[bg]) {
        int a = g_sel[bg * CAND + k];
        int b = bg >> 4;
        atomicAdd(&g_cnt[b * NA + a], 1);
        atomicAdd(&g_gsum[b * NA + a], bg & 15);
    }
}

// ---------------- kernel D: losses ------------------------------------------
__global__ void kLoss(const float* __restrict__ p8, const float* __restrict__ p16,
                      const float* __restrict__ p32, const float* __restrict__ gtb,
                      const int* __restrict__ gtc) {
    int b   = blockIdx.y;
    int tid = threadIdx.x;
    int a   = blockIdx.x * blockDim.x + tid;

    float lb = 0.f, lcf = 0.f, lcl = 0.f, nf = 0.f;
    if (a < NA) {
        int idx = b * NA + a;
        int cnt = g_cnt[idx];
        float cf = g_conf[idx];
        float fg = cnt > 0 ? 1.f : 0.f;
        lcf = fmaxf(cf, 0.f) - cf * fg + log1pf(expf(-fabsf(cf)));
        if (cnt > 0) {
            int gi = (cnt == 1) ? g_gsum[idx] : g_best[idx];
            float miou = g_iou[((size_t)(b * NG + gi)) * NA + a];
            float bx = g_pbox[idx * 4 + 0], by = g_pbox[idx * 4 + 1];
            float bw = g_pbox[idx * 4 + 2], bh = g_pbox[idx * 4 + 3];
            const float* gb = gtb + (b * NG + gi) * 4;
            float cx = gb[0], cy = gb[1], gw = gb[2], gh = gb[3];
            float tlx = fmaxf(bx - bw * 0.5f, cx - gw * 0.5f);
            float tly = fmaxf(by - bh * 0.5f, cy - gh * 0.5f);
            float brx = fminf(bx + bw * 0.5f, cx + gw * 0.5f);
            float bry = fminf(by + bh * 0.5f, cy + gh * 0.5f);
            float iw = fmaxf(brx - tlx, 0.f), ih = fmaxf(bry - tly, 0.f);
            float inter = iw * ih;
            float ioue = inter / (bw * bh + gw * gh - inter + 1e-16f);
            lb = 1.f - ioue * ioue;
            nf = 1.f;
            int tc = gtc[b * NG + gi];
            const float* P; int HW, loc, w; float s;
            level_of(a, b, p8, p16, p32, &P, &HW, &loc, &s, &w);
            P += loc;
            #pragma unroll 4
            for (int c = 0; c < NCLS; c++) {
                float x = P[(5 + c) * HW];
                float t = (c == tc) ? miou : 0.f;
                lcl += fmaxf(x, 0.f) - x * t + log1pf(expf(-fabsf(x)));
            }
        }
    }

    __shared__ float sred[256];
    float vals[4] = {lb, lcf, lcl, nf};
    #pragma unroll
    for (int i = 0; i < 4; i++) {
        sred[tid] = vals[i]; __syncthreads();
        for (int off = 128; off > 0; off >>= 1) {
            if (tid < off) sred[tid] += sred[tid + off];
            __syncthreads();
        }
        if (tid == 0) atomicAdd(&g_acc[i], (double)sred[0]);
        __syncthreads();
    }
}

// ---------------- final combine ----------------------------------------------
__global__ void kFinal(float* out) {
    double nf = g_acc[3];
    if (nf < 1.0) nf = 1.0;
    out[0] = (float)((5.0 * g_acc[0] + g_acc[1] + g_acc[2]) / nf);
}

// ---------------- launcher -----------------------------------------------------
extern "C" void kernel_launch(void* const* d_in, const int* in_sizes, int n_in,
                              void* d_out, int out_size) {
    const float* p8  = (const float*)d_in[0];
    const float* p16 = (const float*)d_in[1];
    const float* p32 = (const float*)d_in[2];
    const float* gtb = (const float*)d_in[3];
    const int*   gtc = (const int*)d_in[4];
    (void)in_sizes; (void)n_in; (void)out_size;

    dim3 grid((NA + 255) / 256, NB);
    kA<<<grid, 256>>>(p8, p16, p32, gtb, gtc);
    kInit<<<(NB * NA + 255) / 256, 256>>>();
    kB<<<NB * NG, 256>>>();
    kScatter<<<(NB * NG * CAND + 255) / 256, 256>>>();
    kLoss<<<grid, 256>>>(p8, p16, p32, gtb, gtc);
    kFinal<<<1, 1>>>((float*)d_out);
}

// round 2
// speedup vs baseline: 1.4373x; 1.4373x over previous
#include <cuda_runtime.h>
#include <math.h>
#include <stdint.h>

#define NB 32
#define NG 16
#define NA 8400
#define NCLS 80
#define CAND 10

// ---------------- scratch (device globals; no allocation allowed) ----------
__device__ float         g_cost[(size_t)NB * NG * NA];   // unmasked cost (union anchors only)
__device__ float         g_iou [(size_t)NB * NG * NA];   // raw pairwise iou (union anchors only)
__device__ float         g_pbox[(size_t)NB * NA * 4];    // decoded boxes (union anchors only)
__device__ unsigned char g_union[(size_t)NB * NA];
__device__ int           g_best[(size_t)NB * NA];        // argmin_g cost (union anchors only)
__device__ int           g_cnt [(size_t)NB * NA];
__device__ int           g_gsum[(size_t)NB * NA];
__device__ int           g_sel [NB * NG * CAND];
__device__ int           g_dynk[NB * NG];
__device__ double        g_acc[4];   // loss_box, loss_conf, loss_cls, n_fg

static __device__ __forceinline__ unsigned long long umin64(unsigned long long a,
                                                            unsigned long long b) {
    return a < b ? a : b;
}

static __device__ __forceinline__ void level_of(int a, int b,
                                                const float* p8, const float* p16, const float* p32,
                                                const float** P, int* HW, int* loc, float* s, int* w) {
    if (a < 6400)      { *P = p8  + (size_t)b * 85 * 6400; *HW = 6400; *loc = a;        *s = 8.f;  *w = 80; }
    else if (a < 8000) { *P = p16 + (size_t)b * 85 * 1600; *HW = 1600; *loc = a - 6400; *s = 16.f; *w = 40; }
    else               { *P = p32 + (size_t)b * 85 * 400;  *HW = 400;  *loc = a - 8000; *s = 32.f; *w = 20; }
}

// 4-value block reduce -> double atomics
static __device__ __forceinline__ void reduce4(float v0, float v1, float v2, float v3) {
    int tid = threadIdx.x, lane = tid & 31, wid = tid >> 5;
    #pragma unroll
    for (int off = 16; off > 0; off >>= 1) {
        v0 += __shfl_down_sync(0xffffffffu, v0, off);
        v1 += __shfl_down_sync(0xffffffffu, v1, off);
        v2 += __shfl_down_sync(0xffffffffu, v2, off);
        v3 += __shfl_down_sync(0xffffffffu, v3, off);
    }
    __shared__ float sw[8][4];
    if (lane == 0) { sw[wid][0] = v0; sw[wid][1] = v1; sw[wid][2] = v2; sw[wid][3] = v3; }
    __syncthreads();
    if (tid == 0) {
        float a0 = 0, a1 = 0, a2 = 0, a3 = 0;
        #pragma unroll
        for (int i = 0; i < 8; i++) { a0 += sw[i][0]; a1 += sw[i][1]; a2 += sw[i][2]; a3 += sw[i][3]; }
        if (a0 != 0.f) atomicAdd(&g_acc[0], (double)a0);
        atomicAdd(&g_acc[1], (double)a1);
        if (a2 != 0.f) atomicAdd(&g_acc[2], (double)a2);
        if (a3 != 0.f) atomicAdd(&g_acc[3], (double)a3);
    }
}

// ---------------- kernel A: decode + cost/iou (union anchors only) ----------
__global__ void kA(const float* __restrict__ p8, const float* __restrict__ p16,
                   const float* __restrict__ p32, const float* __restrict__ gtb,
                   const int* __restrict__ gtc) {
    int b   = blockIdx.y;
    int tid = threadIdx.x;
    int a   = blockIdx.x * blockDim.x + tid;

    __shared__ float sB[NG * 4];
    __shared__ int   sC[NG];
    if (tid < NG * 4) sB[tid] = gtb[b * NG * 4 + tid];
    if (tid < NG)     sC[tid] = gtc[b * NG + tid];
    __syncthreads();

    float softp = 0.f;   // softplus part of conf BCE (all anchors)

    if (a < NA) {
        const float* P; int HW, loc, w; float s;
        level_of(a, b, p8, p16, p32, &P, &HW, &loc, &s, &w);
        P += loc;
        int ix = loc % w, iy = loc / w;
        float xc = ((float)ix + 0.5f) * s;
        float yc = ((float)iy + 0.5f) * s;
        float r2 = 2.5f * s;

        float cf = P[4 * HW];
        softp = fmaxf(cf, 0.f) + log1pf(expf(-fabsf(cf)));   // precise: feeds output

        // ---- geometry pass (pure ALU) ----
        unsigned interM = 0;
        bool uni = false;
        #pragma unroll
        for (int g = 0; g < NG; g++) {
            float cx = sB[g * 4 + 0], cy = sB[g * 4 + 1];
            float gw = sB[g * 4 + 2], gh = sB[g * 4 + 3];
            float gminx = cx - gw * 0.5f, gmaxx = cx + gw * 0.5f;
            float gminy = cy - gh * 0.5f, gmaxy = cy + gh * 0.5f;
            bool inb = (xc - gminx > 0.f) && (gmaxx - xc > 0.f) &&
                       (yc - gminy > 0.f) && (gmaxy - yc > 0.f);
            bool inm = (xc - (cx - r2) > 0.f) && ((cx + r2) - xc > 0.f) &&
                       (yc - (cy - r2) > 0.f) && ((cy + r2) - yc > 0.f);
            if (inb && inm) interM |= (1u << g);
            uni = uni || inb || inm;
        }
        int idx = b * NA + a;
        g_union[idx] = uni ? 1 : 0;

        if (uni) {
            // decode (precise: feeds iou -> dyn_k and box loss)
            float px = P[0], py = P[HW], pw = P[2 * HW], ph = P[3 * HW];
            float bx = (px + (float)ix) * s;
            float by = (py + (float)iy) * s;
            float bw = expf(pw) * s;
            float bh = expf(ph) * s;
            g_pbox[idx * 4 + 0] = bx; g_pbox[idx * 4 + 1] = by;
            g_pbox[idx * 4 + 2] = bw; g_pbox[idx * 4 + 3] = bh;

            // selection math (fast intrinsics OK)
            float vc = __expf(0.5f * cf);          // e^{cf/2}
            float rr = vc * rsqrtf(1.f + vc * vc); // sqrt(sigmoid(cf))

            float s2 = 0.f;
            #pragma unroll 4
            for (int c = 0; c < NCLS; c++) {
                float x = P[(5 + c) * HW];
                float v = __expf(0.5f * x);
                float p = rr * v * rsqrtf(1.f + v * v);   // sqrt(sg*sc)
                s2 += __log2f(fmaxf(1.f - p, 1e-12f));
            }
            float suml1 = s2 * 0.69314718055994531f;

            float areab = bw * bh;
            float bhw = bw * 0.5f, bhh = bh * 0.5f;
            float bestc = 3.402823466e38f;
            int   bestg = 0;
            size_t base = ((size_t)b * NG) * NA + a;

            for (int g = 0; g < NG; g++) {
                float cx = sB[g * 4 + 0], cy = sB[g * 4 + 1];
                float gw = sB[g * 4 + 2], gh = sB[g * 4 + 3];
                int   c  = sC[g];
                float x  = P[(5 + c) * HW];
                float v  = __expf(0.5f * x);
                float p  = rr * v * rsqrtf(1.f + v * v);
                float lp = __logf(fmaxf(p, 1e-12f));
                float l1 = __logf(fmaxf(1.f - p, 1e-12f));
                float cls_cost = -(lp - l1 + suml1);

                float tlx = fmaxf(cx - gw * 0.5f, bx - bhw);
                float tly = fmaxf(cy - gh * 0.5f, by - bhh);
                float brx = fminf(cx + gw * 0.5f, bx + bhw);
                float bry = fminf(cy + gh * 0.5f, by + bhh);
                float iw = fmaxf(brx - tlx, 0.f), ih = fmaxf(bry - tly, 0.f);
                float inter = iw * ih;
                float iou = inter / (gw * gh + areab - inter + 1e-16f);

                float cost = cls_cost - 3.f * __logf(iou + 1e-8f) +
                             (((interM >> g) & 1u) ? 0.f : 100000.f);
                if (cost < bestc) { bestc = cost; bestg = g; }

                g_cost[base + (size_t)g * NA] = cost;
                g_iou [base + (size_t)g * NA] = iou;
            }
            g_best[idx] = bestg;
        }
    }

    // conf softplus into g_acc[1]
    reduce4(0.f, softp, 0.f, 0.f);
}

// ---------------- kernel B: per-(b,g) top-k (cost asc / iou desc) ----------
__global__ void kB() {
    const int T = 256;
    int bg  = blockIdx.x;          // b*16 + g
    int b   = bg >> 4;
    int tid = threadIdx.x;
    size_t cbase = (size_t)bg * NA;
    size_t ubase = (size_t)b * NA;

    unsigned long long keys[CAND], ikeys[CAND];
    #pragma unroll
    for (int k = 0; k < CAND; k++) { keys[k] = ~0ull; ikeys[k] = ~0ull; }

    for (int a = tid; a < NA; a += T) {
        bool u = g_union[ubase + a] != 0;
        float cost = u ? g_cost[cbase + a] : 1e15f;
        unsigned cb = __float_as_uint(cost);
        cb = (cb & 0x80000000u) ? ~cb : (cb | 0x80000000u);
        unsigned long long key = (((unsigned long long)cb) << 32) | (unsigned)a;
        #pragma unroll
        for (int k = 0; k < CAND; k++)
            if (key < keys[k]) { unsigned long long t = keys[k]; keys[k] = key; key = t; }
        float im = u ? g_iou[cbase + a] : 0.f;
        unsigned ib = ~(__float_as_uint(im) | 0x80000000u);
        unsigned long long ikey = (((unsigned long long)ib) << 32) | (unsigned)a;
        #pragma unroll
        for (int k = 0; k < CAND; k++)
            if (ikey < ikeys[k]) { unsigned long long t = ikeys[k]; ikeys[k] = ikey; ikey = t; }
    }

    __shared__ unsigned long long sk[T * CAND];
    __shared__ unsigned long long red[T];

    #pragma unroll
    for (int k = 0; k < CAND; k++) sk[tid * CAND + k] = keys[k];
    __syncthreads();
    for (int k = 0; k < CAND; k++) {
        unsigned long long m = ~0ull;
        for (int j = tid; j < T * CAND; j += T) m = umin64(m, sk[j]);
        red[tid] = m; __syncthreads();
        for (int off = T / 2; off > 0; off >>= 1) {
            if (tid < off) red[tid] = umin64(red[tid], red[tid + off]);
            __syncthreads();
        }
        unsigned long long best = red[0];
        if (tid == 0) g_sel[bg * CAND + k] = (int)(best & 0xffffffffu);
        for (int j = tid; j < T * CAND; j += T) if (sk[j] == best) sk[j] = ~0ull;
        __syncthreads();
    }

    #pragma unroll
    for (int k = 0; k < CAND; k++) sk[tid * CAND + k] = ikeys[k];
    __syncthreads();
    float sum = 0.f;
    for (int k = 0; k < CAND; k++) {
        unsigned long long m = ~0ull;
        for (int j = tid; j < T * CAND; j += T) m = umin64(m, sk[j]);
        red[tid] = m; __syncthreads();
        for (int off = T / 2; off > 0; off >>= 1) {
            if (tid < off) red[tid] = umin64(red[tid], red[tid + off]);
            __syncthreads();
        }
        unsigned long long best = red[0];
        unsigned key32 = (unsigned)(best >> 32);
        sum += __uint_as_float((~key32) & 0x7fffffffu);
        for (int j = tid; j < T * CAND; j += T) if (sk[j] == best) sk[j] = ~0ull;
        __syncthreads();
    }
    if (tid == 0) {
        int dk = (int)sum;
        g_dynk[bg] = dk < 1 ? 1 : dk;
    }
}

// ---------------- init scratch ----------------------------------------------
__global__ void kInit() {
    int i = blockIdx.x * blockDim.x + threadIdx.x;
    if (i < NB * NA) { g_cnt[i] = 0; g_gsum[i] = 0; }
    if (i < 4) g_acc[i] = 0.0;
}

// ---------------- scatter selections ----------------------------------------
__global__ void kScatter() {
    int e = blockIdx.x * blockDim.x + threadIdx.x;
    if (e >= NB * NG * CAND) return;
    int k  = e % CAND;
    int bg = e / CAND;
    if (k < g_dynk[bg]) {
        int a = g_sel[bg * CAND + k];
        int b = bg >> 4;
        atomicAdd(&g_cnt[b * NA + a], 1);
        atomicAdd(&g_gsum[b * NA + a], bg & 15);
    }
}

// ---------------- kernel D: fg-only losses ----------------------------------
__global__ void kLoss(const float* __restrict__ p8, const float* __restrict__ p16,
                      const float* __restrict__ p32, const float* __restrict__ gtb,
                      const int* __restrict__ gtc) {
    int b   = blockIdx.y;
    int tid = threadIdx.x;
    int a   = blockIdx.x * blockDim.x + tid;

    float lb = 0.f, lcf = 0.f, lcl = 0.f, nf = 0.f;
    if (a < NA) {
        int idx = b * NA + a;
        int cnt = g_cnt[idx];
        if (cnt > 0) {
            int gi = (cnt == 1) ? g_gsum[idx] : g_best[idx];
            float miou = g_iou[((size_t)(b * NG + gi)) * NA + a];
            float bx = g_pbox[idx * 4 + 0], by = g_pbox[idx * 4 + 1];
            float bw = g_pbox[idx * 4 + 2], bh = g_pbox[idx * 4 + 3];
            const float* gb = gtb + (b * NG + gi) * 4;
            float cx = gb[0], cy = gb[1], gw = gb[2], gh = gb[3];
            float tlx = fmaxf(bx - bw * 0.5f, cx - gw * 0.5f);
            float tly = fmaxf(by - bh * 0.5f, cy - gh * 0.5f);
            float brx = fminf(bx + bw * 0.5f, cx + gw * 0.5f);
            float bry = fminf(by + bh * 0.5f, cy + gh * 0.5f);
            float iw = fmaxf(brx - tlx, 0.f), ih = fmaxf(bry - tly, 0.f);
            float inter = iw * ih;
            float ioue = inter / (bw * bh + gw * gh - inter + 1e-16f);
            lb = 1.f - ioue * ioue;
            nf = 1.f;
            int tc = gtc[b * NG + gi];
            const float* P; int HW, loc, w; float s;
            level_of(a, b, p8, p16, p32, &P, &HW, &loc, &s, &w);
            P += loc;
            lcf = -P[4 * HW];   // -x*fg term; softplus part was summed in kA
            #pragma unroll 4
            for (int c = 0; c < NCLS; c++) {
                float x = P[(5 + c) * HW];
                float t = (c == tc) ? miou : 0.f;
                lcl += fmaxf(x, 0.f) - x * t + log1pf(expf(-fabsf(x)));
            }
        }
    }
    reduce4(lb, lcf, lcl, nf);
}

// ---------------- final combine ----------------------------------------------
__global__ void kFinal(float* out) {
    double nf = g_acc[3];
    if (nf < 1.0) nf = 1.0;
    out[0] = (float)((5.0 * g_acc[0] + g_acc[1] + g_acc[2]) / nf);
}

// ---------------- launcher -----------------------------------------------------
extern "C" void kernel_launch(void* const* d_in, const int* in_sizes, int n_in,
                              void* d_out, int out_size) {
    const float* p8  = (const float*)d_in[0];
    const float* p16 = (const float*)d_in[1];
    const float* p32 = (const float*)d_in[2];
    const float* gtb = (const float*)d_in[3];
    const int*   gtc = (const int*)d_in[4];
    (void)in_sizes; (void)n_in; (void)out_size;

    dim3 grid((NA + 255) / 256, NB);
    kInit<<<(NB * NA + 255) / 256, 256>>>();
    kA<<<grid, 256>>>(p8, p16, p32, gtb, gtc);
    kB<<<NB * NG, 256>>>();
    kScatter<<<(NB * NG * CAND + 255) / 256, 256>>>();
    kLoss<<<grid, 256>>>(p8, p16, p32, gtb, gtc);
    kFinal<<<1, 1>>>((float*)d_out);
}